// round 10
// baseline (speedup 1.0000x reference)
#include <cuda_runtime.h>
#include <cuda_bf16.h>
#include <cstdint>

// Plane2Depth: out[b,0,H,W] = 1 / max( s*(p*u + q*v + r), 0.1 )
// [p,q,r,s] = Wmat @ feat[b,:,H/4,W/4];  norm cancels algebraically.
//
// R9: anti-phase-locking. Block = 4 input rows, software pipelined:
//   - loads for row r+1 prefetched before row r's MUFU burst
//   - double-buffered SMEM; TMA bulk store of row r-1 drains during
//     compute of row r (wait_group 1, not the serial wait_group 0 tail)
//   - grid = 768 blocks -> single wave, no wave transitions
// Steady state: each SM has warps concurrently in load/MUFU/STS/TMA phases.

#define IN_H   192
#define IN_W   192
#define BATCH  16
#define OUT_HW 768            // 192*4
#define PLANE  (IN_H * IN_W)
#define ROWS   4              // input rows per block
#define TILE_BYTES (4 * OUT_HW * 4)   // 12288 per input row

__global__ __launch_bounds__(IN_W)
void plane2depth_kernel(const float* __restrict__ feat,
                        const float4* __restrict__ Wmat,
                        float* __restrict__ out)
{
    __shared__ __align__(16) float sm[2][4][OUT_HW];   // 2 x 12288 B

    const int w  = threadIdx.x;        // input column (0..191)
    const int h0 = blockIdx.x * ROWS;  // first input row of this block
    const int b  = blockIdx.y;         // batch

    // ---- W matrix: 4 vector loads, uniform broadcast, L1-resident ----
    float4 m0 = __ldg(Wmat + 0);
    float4 m1 = __ldg(Wmat + 1);
    float4 m2 = __ldg(Wmat + 2);
    float4 m3 = __ldg(Wmat + 3);

    const float* fp = feat + (size_t)b * 4 * PLANE + (size_t)h0 * IN_W + w;

    // prefetch row 0 channels
    float c0 = fp[0];
    float c1 = fp[PLANE];
    float c2 = fp[2 * PLANE];
    float c3 = fp[3 * PLANE];

    const float UV0 = -0.375f, UV1 = -0.125f, UV2 = 0.125f, UV3 = 0.375f;
    const float DMIN = 0.1f;   // 1.0 / MAX_DEPTH

#pragma unroll
    for (int r = 0; r < ROWS; r++) {
        // ---- prefetch next row's channels (issues before the MUFU burst) ----
        float n0 = 0.f, n1 = 0.f, n2 = 0.f, n3 = 0.f;
        if (r + 1 < ROWS) {
            const float* np = fp + (size_t)(r + 1) * IN_W;
            n0 = np[0];
            n1 = np[PLANE];
            n2 = np[2 * PLANE];
            n3 = np[3 * PLANE];
        }

        // ---- make sure buffer (r&1) is free: copy issued at r-2 must be done ----
        if (r >= 2) {
            if (w == 0)
                asm volatile("cp.async.bulk.wait_group 1;" ::: "memory");
            __syncthreads();
        }

        // ---- plane equation for this pixel ----
        float p = fmaf(m0.x, c0, fmaf(m0.y, c1, fmaf(m0.z, c2, m0.w * c3)));
        float q = fmaf(m1.x, c0, fmaf(m1.y, c1, fmaf(m1.z, c2, m1.w * c3)));
        float t = fmaf(m2.x, c0, fmaf(m2.y, c1, fmaf(m2.z, c2, m2.w * c3)));
        float s = fmaf(m3.x, c0, fmaf(m3.y, c1, fmaf(m3.z, c2, m3.w * c3)));

        float sp = s * p, sq = s * q, st = s * t;
        float pu0 = sp * UV0, pu1 = sp * UV1, pu2 = sp * UV2, pu3 = sp * UV3;

        float* smr = &sm[r & 1][0][4 * w];
#pragma unroll
        for (int j = 0; j < 4; j++) {           // output sub-row (v index)
            float vj   = (float)j * 0.25f - 0.375f;
            float base = fmaf(sq, vj, st);
            float4 o;
            float d;
            d = pu0 + base; d = fmaxf(d, DMIN); o.x = __fdividef(1.0f, d);
            d = pu1 + base; d = fmaxf(d, DMIN); o.y = __fdividef(1.0f, d);
            d = pu2 + base; d = fmaxf(d, DMIN); o.z = __fdividef(1.0f, d);
            d = pu3 + base; d = fmaxf(d, DMIN); o.w = __fdividef(1.0f, d);
            *(float4*)(smr + (size_t)j * OUT_HW) = o;   // STS.128, conflict-free
        }

        __syncthreads();

        // ---- issue bulk store for this row; do NOT drain (overlap with next) ----
        if (w == 0) {
            float* dst = out + ((size_t)b * OUT_HW + (size_t)(4 * (h0 + r))) * OUT_HW;
            uint32_t saddr;
            asm volatile("{ .reg .u64 t; cvta.to.shared.u64 t, %1; cvt.u32.u64 %0, t; }"
                         : "=r"(saddr) : "l"(&sm[r & 1][0][0]));
            asm volatile("fence.proxy.async.shared::cta;" ::: "memory");
            asm volatile("cp.async.bulk.global.shared::cta.bulk_group [%0], [%1], %2;"
                         :: "l"(dst), "r"(saddr), "r"((int)TILE_BYTES) : "memory");
            asm volatile("cp.async.bulk.commit_group;" ::: "memory");
        }

        // rotate prefetched registers
        c0 = n0; c1 = n1; c2 = n2; c3 = n3;
    }

    // drain all outstanding copies before SMEM is reused by another block
    if (w == 0)
        asm volatile("cp.async.bulk.wait_group 0;" ::: "memory");
    __syncthreads();
}

extern "C" void kernel_launch(void* const* d_in, const int* in_sizes, int n_in,
                              void* d_out, int out_size)
{
    const float*  feat = (const float*)d_in[0];    // (16,4,192,192) f32
    const float4* Wmat = (const float4*)d_in[1];   // (4,4) f32
    float* out = (float*)d_out;                    // (16,1,768,768) f32

    dim3 grid(IN_H / ROWS, BATCH);   // 48 x 16 = 768 blocks (single wave)
    dim3 block(IN_W);                // 192 threads = one input row
    plane2depth_kernel<<<grid, block>>>(feat, Wmat, out);
}

// round 11
// speedup vs baseline: 1.2149x; 1.2149x over previous
#include <cuda_runtime.h>
#include <cuda_bf16.h>
#include <cstdint>

// Plane2Depth: out[b,0,H,W] = 1 / max( s*(p*u + q*v + r), 0.1 )
// [p,q,r,s] = Wmat @ feat[b,:,H/4,W/4];  norm cancels algebraically.
//
// R10 = refined R7 (best: 9.47us ncu). Changes:
//  - 2 input rows per block (384 thr, 2D block 192x2): their 8 output rows
//    are 24576 CONTIGUOUS bytes -> ONE cp.async.bulk per block (half the
//    TMA ops and half the drain tails of R7).
//  - no trailing __syncthreads: only thread 0 waits on the bulk copy; the
//    other 11 warps retire immediately (SMEM is freed at full-CTA exit, so
//    the in-flight TMA read stays safe).
//  - fence.proxy.async.shared::cta between STS and the bulk-engine read
//    (generic->async proxy ordering; R7 relied on luck).
//  - occupancy: 12 warps/block, 24.6KB smem -> 5 blocks/SM (60/64 warps).

#define IN_H   192
#define IN_W   192
#define BATCH  16
#define OUT_HW 768            // 192*4
#define PLANE  (IN_H * IN_W)
#define ROWS   2              // input rows per block
#define TILE_BYTES (ROWS * 4 * OUT_HW * 4)   // 24576

__global__ __launch_bounds__(IN_W * ROWS)
void plane2depth_kernel(const float* __restrict__ feat,
                        const float4* __restrict__ Wmat,
                        float* __restrict__ out)
{
    __shared__ __align__(16) float sm[ROWS][4][OUT_HW];   // 24576 B

    const int w  = threadIdx.x;                    // input column (0..191)
    const int ry = threadIdx.y;                    // row within block (0..1)
    const int h  = blockIdx.x * ROWS + ry;         // input row
    const int b  = blockIdx.y;                     // batch

    // ---- load 4 channels of this pixel (each warp-coalesced 128B) ----
    const float* fp = feat + (size_t)b * 4 * PLANE + (size_t)h * IN_W + w;
    float f0 = fp[0];
    float f1 = fp[PLANE];
    float f2 = fp[2 * PLANE];
    float f3 = fp[3 * PLANE];

    // ---- W matrix: 4 vector loads, uniform broadcast, L1-resident ----
    float4 m0 = __ldg(Wmat + 0);
    float4 m1 = __ldg(Wmat + 1);
    float4 m2 = __ldg(Wmat + 2);
    float4 m3 = __ldg(Wmat + 3);

    float p = fmaf(m0.x, f0, fmaf(m0.y, f1, fmaf(m0.z, f2, m0.w * f3)));
    float q = fmaf(m1.x, f0, fmaf(m1.y, f1, fmaf(m1.z, f2, m1.w * f3)));
    float t = fmaf(m2.x, f0, fmaf(m2.y, f1, fmaf(m2.z, f2, m2.w * f3)));
    float s = fmaf(m3.x, f0, fmaf(m3.y, f1, fmaf(m3.z, f2, m3.w * f3)));

    // fold s:  d = sp*u + sq*v + sr
    float sp = s * p, sq = s * q, st = s * t;

    const float DMIN = 0.1f;   // 1.0 / MAX_DEPTH
    float pu0 = sp * -0.375f, pu1 = sp * -0.125f,
          pu2 = sp *  0.125f, pu3 = sp *  0.375f;

    float* smr = &sm[ry][0][4 * w];
#pragma unroll
    for (int j = 0; j < 4; j++) {            // output sub-row (v index)
        float vj   = (float)j * 0.25f - 0.375f;
        float base = fmaf(sq, vj, st);
        float4 o;
        float d;
        d = pu0 + base; d = fmaxf(d, DMIN); o.x = __fdividef(1.0f, d);
        d = pu1 + base; d = fmaxf(d, DMIN); o.y = __fdividef(1.0f, d);
        d = pu2 + base; d = fmaxf(d, DMIN); o.z = __fdividef(1.0f, d);
        d = pu3 + base; d = fmaxf(d, DMIN); o.w = __fdividef(1.0f, d);
        *(float4*)(smr + (size_t)j * OUT_HW) = o;   // STS.128, conflict-free
    }

    __syncthreads();   // all STS complete before the bulk engine reads SMEM

    // One bulk copy: 24576B -> output rows [8*blockIdx.x, 8*blockIdx.x+8).
    // Only thread 0 waits; every other warp retires now. SMEM stays
    // allocated until the whole CTA (i.e. thread 0) exits.
    if (threadIdx.x == 0 && threadIdx.y == 0) {
        float* dst = out + ((size_t)b * OUT_HW + (size_t)(8 * blockIdx.x)) * OUT_HW;
        uint32_t saddr;
        asm volatile("{ .reg .u64 t; cvta.to.shared.u64 t, %1; cvt.u32.u64 %0, t; }"
                     : "=r"(saddr) : "l"(&sm[0][0][0]));
        asm volatile("fence.proxy.async.shared::cta;" ::: "memory");
        asm volatile("cp.async.bulk.global.shared::cta.bulk_group [%0], [%1], %2;"
                     :: "l"(dst), "r"(saddr), "r"((int)TILE_BYTES) : "memory");
        asm volatile("cp.async.bulk.commit_group;" ::: "memory");
        asm volatile("cp.async.bulk.wait_group 0;" ::: "memory");
    }
}

extern "C" void kernel_launch(void* const* d_in, const int* in_sizes, int n_in,
                              void* d_out, int out_size)
{
    const float*  feat = (const float*)d_in[0];    // (16,4,192,192) f32
    const float4* Wmat = (const float4*)d_in[1];   // (4,4) f32
    float* out = (float*)d_out;                    // (16,1,768,768) f32

    dim3 grid(IN_H / ROWS, BATCH);   // 96 x 16 = 1536 blocks
    dim3 block(IN_W, ROWS);          // 192 x 2 = 384 threads
    plane2depth_kernel<<<grid, block>>>(feat, Wmat, out);
}